// round 3
// baseline (speedup 1.0000x reference)
#include <cuda_runtime.h>
#include <cstdint>

// Static config (Fp8Padding num_gemms=8, align=16)
// M_SPLITS       = {4091, 8177, 2045, 4093, 6133, 1021, 4085, 8189}
// PADDED_SPLITS  = {4096, 8192, 2048, 4096, 6144, 1024, 4096, 8192}
// HIDDEN = 2048 floats = 512 float4 per row

#define HIDDEN4     512                      // float4 per row
#define TOTAL_OUT4  (37888 * HIDDEN4)        // 19,398,656 float4
#define VPT         8                        // float4 per thread
#define TPB         256
#define CHUNK       (TPB * VPT)              // 2048 float4 per block

__constant__ int c_out_start[8] = {0, 4096, 12288, 14336, 18432, 24576, 25600, 29696};
__constant__ int c_in_start [8] = {0, 4091, 12268, 14313, 18406, 24539, 25560, 29645};
__constant__ int c_m        [8] = {4091, 8177, 2045, 4093, 6133, 1021, 4085, 8189};

__global__ void __launch_bounds__(TPB) fp8_padding_kernel(
    const float4* __restrict__ in, float4* __restrict__ out)
{
    int base = blockIdx.x * CHUNK + threadIdx.x;

    float4 v[VPT];

    // Front-batched independent streaming loads (MLP_p1 = 8).
    // Pad rows predicated off (gather address would run past input end).
    #pragma unroll
    for (int k = 0; k < VPT; k++) {
        int idx = base + k * TPB;
        int row = idx >> 9;
        int col = idx & (HIDDEN4 - 1);

        // Branch-free segment lookup over the 8 static padded-row boundaries.
        int seg = (row >= 4096)  + (row >= 12288) + (row >= 14336) + (row >= 18432)
                + (row >= 24576) + (row >= 25600) + (row >= 29696);

        int local = row - c_out_start[seg];
        v[k] = make_float4(0.f, 0.f, 0.f, 0.f);
        if (local < c_m[seg]) {
            int src_row = c_in_start[seg] + local;
            v[k] = __ldcs(&in[(long long)src_row * HIDDEN4 + col]);  // evict-first
        }
    }

    #pragma unroll
    for (int k = 0; k < VPT; k++) {
        __stcs(&out[base + k * TPB], v[k]);                          // evict-first
    }
}

extern "C" void kernel_launch(void* const* d_in, const int* in_sizes, int n_in,
                              void* d_out, int out_size)
{
    const float4* in  = (const float4*)d_in[0];
    float4*       out = (float4*)d_out;
    // TOTAL_OUT4 = 19,398,656 = 9,472 * 2048 exactly
    fp8_padding_kernel<<<TOTAL_OUT4 / CHUNK, TPB>>>(in, out);
}